// round 6
// baseline (speedup 1.0000x reference)
#include <cuda_runtime.h>

#define N_NODES 100000
#define N_EDGES 1600000
#define N_GRAPH 64
#define H 128
// Wf1 input dim = H + SV + AD = 128 + 64 + 32
#define ZDIM 224

// ---------------- scratch (device globals: allocation-free) ----------------
__device__ float g_deg[N_NODES];
__device__ float g_dis[N_NODES];
__device__ float g_h [(size_t)N_NODES * H];   // h' = dis * (A @ W)  (gather source)
__device__ float g_s1[(size_t)N_NODES * H];   // layer-1 accumulator (seeded with h')
__device__ float g_s2[(size_t)N_NODES * H];   // layer-2 accumulator (seeded with h')
__device__ float g_pool[N_GRAPH * H];
__device__ float g_cnt[N_GRAPH];

// ---------------- small setup kernels ----------------
__global__ void k_init() {
    int i = blockIdx.x * blockDim.x + threadIdx.x;
    if (i < N_NODES) g_deg[i] = 1.0f;          // self-loop: deg = in_deg + 1
    if (i < N_GRAPH * H) g_pool[i] = 0.0f;
    if (i < N_GRAPH) g_cnt[i] = 0.0f;
}

// NOTE: edge_index/batch arrive as int32 (JAX x64 disabled downcasts jnp.int64)
__global__ void k_deg(const int* __restrict__ ei) {
    int i = blockIdx.x * blockDim.x + threadIdx.x;
    if (i < N_EDGES) {
        int d = ei[N_EDGES + i];               // dst row of edge_index
        if ((unsigned)d < N_NODES) atomicAdd(&g_deg[d], 1.0f);
    }
}

__global__ void k_rsqrt() {
    int i = blockIdx.x * blockDim.x + threadIdx.x;
    if (i < N_NODES) g_dis[i] = rsqrtf(g_deg[i]);
}

// ---------------- GEMM: out = dis[row] * (A @ W), dual-write ----------------
// BM=64 rows x full 128 cols x full K=128 in one smem pass.
// 256 threads as 16(ty) x 16(tx); microtile 4 rows x 8 cols.
// LAYER==0: A = x (ext), sout = g_s1.   LAYER==1: A = relu(dis*g_s1 + b1), sout = g_s2.
#define ASTR 132                                  // pad: float4-aligned, conflict-free stores
#define GEMM_SMEM ((64 * ASTR + 128 * 128) * 4)   // 99328 B

template<bool TRANS, int LAYER>
__global__ __launch_bounds__(256) void k_gemm(const float* __restrict__ Aext,
                                              const float* __restrict__ W,
                                              const float* __restrict__ bprev) {
    extern __shared__ float smem[];
    float* As = smem;                  // [64][ASTR]
    float* Ws = smem + 64 * ASTR;      // [128][128]

    const float* A = (LAYER == 0) ? Aext : g_s1;
    float* hout = g_h;
    float* sout = (LAYER == 0) ? g_s1 : g_s2;

    int tid = threadIdx.x;
    int row0 = blockIdx.x * 64;

    // stage W (128x128 = 4096 float4)
    const float4* W4 = (const float4*)W;
    float4* Ws4 = (float4*)Ws;
#pragma unroll
    for (int i = 0; i < 16; i++) Ws4[tid + i * 256] = W4[tid + i * 256];

    // stage A tile (64x128 = 2048 float4), optional fused relu(dis*s1 + b1)
#pragma unroll
    for (int i = 0; i < 8; i++) {
        int j = tid + i * 256;
        int r = j >> 5, c4 = j & 31;           // one warp == one full row
        int grow = row0 + r;
        float4 v = make_float4(0.f, 0.f, 0.f, 0.f);
        if (grow < N_NODES) {
            v = *(const float4*)&A[(size_t)grow * H + c4 * 4];
            if (TRANS) {
                float d = g_dis[grow];
                float4 bb = *(const float4*)&bprev[c4 * 4];
                v.x = fmaxf(fmaf(d, v.x, bb.x), 0.f);
                v.y = fmaxf(fmaf(d, v.y, bb.y), 0.f);
                v.z = fmaxf(fmaf(d, v.z, bb.z), 0.f);
                v.w = fmaxf(fmaf(d, v.w, bb.w), 0.f);
            }
        }
        *(float4*)&As[r * ASTR + c4 * 4] = v;
    }
    __syncthreads();

    int tx = tid & 15, ty = tid >> 4;
    float acc[4][8];
#pragma unroll
    for (int i = 0; i < 4; i++)
#pragma unroll
        for (int j = 0; j < 8; j++) acc[i][j] = 0.f;

    const float* Asr = &As[(ty * 4) * ASTR];
#pragma unroll 8
    for (int k = 0; k < 128; k++) {
        float av[4];
#pragma unroll
        for (int i = 0; i < 4; i++) av[i] = Asr[i * ASTR + k];   // broadcast LDS
        float4 b0 = *(const float4*)&Ws[k * 128 + tx * 8];
        float4 b1 = *(const float4*)&Ws[k * 128 + tx * 8 + 4];
        float bv[8] = {b0.x, b0.y, b0.z, b0.w, b1.x, b1.y, b1.z, b1.w};
#pragma unroll
        for (int i = 0; i < 4; i++)
#pragma unroll
            for (int j = 0; j < 8; j++) acc[i][j] = fmaf(av[i], bv[j], acc[i][j]);
    }

    // epilogue: scale by dis[row], write h' twice (gather src + self-loop seed)
#pragma unroll
    for (int i = 0; i < 4; i++) {
        int grow = row0 + ty * 4 + i;
        if (grow >= N_NODES) continue;
        float d = g_dis[grow];
        float4 o0 = make_float4(acc[i][0] * d, acc[i][1] * d, acc[i][2] * d, acc[i][3] * d);
        float4 o1 = make_float4(acc[i][4] * d, acc[i][5] * d, acc[i][6] * d, acc[i][7] * d);
        size_t off = (size_t)grow * H + tx * 8;
        *(float4*)&hout[off]     = o0;
        *(float4*)&hout[off + 4] = o1;
        *(float4*)&sout[off]     = o0;
        *(float4*)&sout[off + 4] = o1;
    }
}

// ---------------- edge scatter: s[dst] += h'[src] ----------------
// one warp per edge: 32 lanes x float4 gather, vector red (fire-and-forget)
template<int LAYER>
__global__ __launch_bounds__(256) void k_scatter(const int* __restrict__ ei) {
    int widx = (blockIdx.x * blockDim.x + threadIdx.x) >> 5;
    int lane = threadIdx.x & 31;
    if (widx >= N_EDGES) return;
    int s = __ldg(&ei[widx]);
    int d = __ldg(&ei[N_EDGES + widx]);
    if ((unsigned)s >= N_NODES || (unsigned)d >= N_NODES) return;  // dtype-theory guard
    float* sdst = (LAYER == 0) ? g_s1 : g_s2;
    float4 v = *(const float4*)&g_h[(size_t)s * H + lane * 4];
    float* p = &sdst[(size_t)d * H + lane * 4];
    asm volatile("red.global.add.v4.f32 [%0], {%1,%2,%3,%4};"
                 :: "l"(p), "f"(v.x), "f"(v.y), "f"(v.z), "f"(v.w)
                 : "memory");
}

// ---------------- global mean pool with fused relu(dis*s2 + b2) ----------------
#define POOL_CHUNK 64
__global__ __launch_bounds__(128) void k_pool(const int* __restrict__ batch,
                                              const float* __restrict__ b2) {
    int r0 = blockIdx.x * POOL_CHUNK;
    if (r0 >= N_NODES) return;
    int r1 = min(r0 + POOL_CHUNK, N_NODES);
    int f = threadIdx.x;                 // one thread per feature
    float bb = b2[f];
    int cur = batch[r0];
    float acc = 0.f, c = 0.f;
    for (int r = r0; r < r1; r++) {
        int g = batch[r];                // sorted -> rare flushes, uniform branch
        if (g != cur) {
            atomicAdd(&g_pool[cur * H + f], acc);
            if (f == 0) atomicAdd(&g_cnt[cur], c);
            acc = 0.f; c = 0.f; cur = g;
        }
        float v = fmaxf(fmaf(g_dis[r], g_s2[(size_t)r * H + f], bb), 0.f);
        acc += v; c += 1.f;
    }
    atomicAdd(&g_pool[cur * H + f], acc);
    if (f == 0) atomicAdd(&g_cnt[cur], c);
}

// ---------------- head MLP: 64 blocks, one per graph ----------------
__global__ __launch_bounds__(256) void k_mlp(const float* __restrict__ sv,
                                             const float* __restrict__ act,
                                             const float* __restrict__ Wf1, const float* __restrict__ bf1,
                                             const float* __restrict__ Wf2, const float* __restrict__ bf2,
                                             const float* __restrict__ Wo,  const float* __restrict__ bo,
                                             float* __restrict__ out) {
    int g = blockIdx.x;
    int t = threadIdx.x;
    __shared__ float z[ZDIM];
    __shared__ float z1[256];
    __shared__ float z2[256];
    __shared__ float red[8];

    if (t < ZDIM) {
        float v;
        if (t < 128)      v = g_pool[g * H + t] / fmaxf(g_cnt[g], 1.0f);
        else if (t < 192) v = sv[g * 64 + (t - 128)];
        else              v = act[g * 32 + (t - 192)];
        z[t] = v;
    }
    __syncthreads();

    float a = bf1[t];
#pragma unroll 8
    for (int k = 0; k < ZDIM; k++) a = fmaf(z[k], Wf1[k * 256 + t], a);
    z1[t] = fmaxf(a, 0.f);
    __syncthreads();

    a = bf2[t];
#pragma unroll 8
    for (int k = 0; k < 256; k++) a = fmaf(z1[k], Wf2[k * 256 + t], a);
    z2[t] = fmaxf(a, 0.f);
    __syncthreads();

    float p = z2[t] * Wo[t];
#pragma unroll
    for (int o = 16; o > 0; o >>= 1) p += __shfl_down_sync(0xffffffffu, p, o);
    if ((t & 31) == 0) red[t >> 5] = p;
    __syncthreads();
    if (t == 0) {
        float sacc = 0.f;
#pragma unroll
        for (int i = 0; i < 8; i++) sacc += red[i];
        out[g] = sacc + bo[0];
    }
}

// ---------------- launch ----------------
extern "C" void kernel_launch(void* const* d_in, const int* in_sizes, int n_in,
                              void* d_out, int out_size) {
    const float* x     = (const float*)d_in[0];
    const int*   ei    = (const int*)d_in[1];
    const int*   batch = (const int*)d_in[2];
    const float* sv    = (const float*)d_in[3];
    const float* act   = (const float*)d_in[4];
    const float* W1    = (const float*)d_in[5];
    const float* b1    = (const float*)d_in[6];
    const float* W2    = (const float*)d_in[7];
    const float* b2    = (const float*)d_in[8];
    const float* Wf1   = (const float*)d_in[9];
    const float* bf1   = (const float*)d_in[10];
    const float* Wf2   = (const float*)d_in[11];
    const float* bf2   = (const float*)d_in[12];
    const float* Wo    = (const float*)d_in[13];
    const float* bo    = (const float*)d_in[14];
    float* out = (float*)d_out;

    // opt into >48KB dynamic smem (host-side attribute, capture-safe, idempotent)
    cudaFuncSetAttribute(k_gemm<false, 0>, cudaFuncAttributeMaxDynamicSharedMemorySize, GEMM_SMEM);
    cudaFuncSetAttribute(k_gemm<true, 1>,  cudaFuncAttributeMaxDynamicSharedMemorySize, GEMM_SMEM);

    k_init <<<(N_NODES + 255) / 256, 256>>>();
    k_deg  <<<(N_EDGES + 255) / 256, 256>>>(ei);
    k_rsqrt<<<(N_NODES + 255) / 256, 256>>>();

    int gemm_blocks = (N_NODES + 63) / 64;
    int scat_blocks = (int)(((long long)N_EDGES * 32 + 255) / 256);

    k_gemm<false, 0><<<gemm_blocks, 256, GEMM_SMEM>>>(x, W1, b1);
    k_scatter<0>    <<<scat_blocks, 256>>>(ei);
    k_gemm<true, 1> <<<gemm_blocks, 256, GEMM_SMEM>>>(x, W2, b1);
    k_scatter<1>    <<<scat_blocks, 256>>>(ei);

    k_pool<<<(N_NODES + POOL_CHUNK - 1) / POOL_CHUNK, 128>>>(batch, b2);
    k_mlp <<<N_GRAPH, 256>>>(sv, act, Wf1, bf1, Wf2, bf2, Wo, bo, out);
}

// round 7
// speedup vs baseline: 2.0868x; 2.0868x over previous
#include <cuda_runtime.h>
#include <cuda_fp16.h>

#define N_NODES 100000
#define N_EDGES 1600000
#define N_GRAPH 64
#define H 128
// Wf1 input dim = H + SV + AD = 128 + 64 + 32
#define ZDIM 224

// ---------------- scratch (device globals: allocation-free) ----------------
__device__ float  g_deg[N_NODES];
__device__ float  g_dis[N_NODES];
__device__ __half g_h [(size_t)N_NODES * H];   // h' = dis * (A @ W) (gather source, fp16)
__device__ __half g_s1[(size_t)N_NODES * H];   // layer-1 accumulator (seeded with h')
__device__ __half g_s2[(size_t)N_NODES * H];   // layer-2 accumulator (seeded with h')
__device__ float  g_pool[N_GRAPH * H];
__device__ float  g_cnt[N_GRAPH];

// ---------------- small setup kernels ----------------
__global__ void k_init() {
    int i = blockIdx.x * blockDim.x + threadIdx.x;
    if (i < N_NODES) g_deg[i] = 1.0f;          // self-loop: deg = in_deg + 1
    if (i < N_GRAPH * H) g_pool[i] = 0.0f;
    if (i < N_GRAPH) g_cnt[i] = 0.0f;
}

__global__ void k_deg(const int* __restrict__ ei) {
    int i = blockIdx.x * blockDim.x + threadIdx.x;
    if (i < N_EDGES) {
        int d = ei[N_EDGES + i];
        if ((unsigned)d < N_NODES) atomicAdd(&g_deg[d], 1.0f);
    }
}

__global__ void k_rsqrt() {
    int i = blockIdx.x * blockDim.x + threadIdx.x;
    if (i < N_NODES) g_dis[i] = rsqrtf(g_deg[i]);
}

// ---------------- tf32 tensor-core GEMM: out = dis[row]*(A @ W), dual fp16 write ----
// CTA tile 128(M) x 128(N) x 128(K, fully staged). 256 threads = 8 warps (4m x 2n),
// warp tile 32x64 via mma.sync.m16n8k8 tf32 (2 m-frags x 8 n-frags per k-step).
// smem strides chosen conflict-free: As stride 132 (row*4+k spans 32 banks),
// Ws stride 136 (k*8+n spans 32 banks).
#define BM 128
#define ASTR 132
#define WSTR 136
#define GEMM_SMEM ((BM * ASTR + 128 * WSTR + 256) * 4)   // 138240 B

__device__ __forceinline__ float f2tf32(float f) {
    unsigned u;
    asm("cvt.rna.tf32.f32 %0, %1;" : "=r"(u) : "f"(f));
    return __uint_as_float(u);
}

__device__ __forceinline__ void mma_tf32(float& d0, float& d1, float& d2, float& d3,
                                         unsigned a0, unsigned a1, unsigned a2, unsigned a3,
                                         unsigned b0, unsigned b1) {
    asm volatile("mma.sync.aligned.m16n8k8.row.col.f32.tf32.tf32.f32 "
                 "{%0,%1,%2,%3}, {%4,%5,%6,%7}, {%8,%9}, {%0,%1,%2,%3};"
                 : "+f"(d0), "+f"(d1), "+f"(d2), "+f"(d3)
                 : "r"(a0), "r"(a1), "r"(a2), "r"(a3), "r"(b0), "r"(b1));
}

// LAYER==0: A = x (fp32 ext), sout = g_s1.  LAYER==1: A = relu(dis*g_s1 + b1) (fp16), sout = g_s2.
template<int LAYER>
__global__ __launch_bounds__(256) void k_gemm(const float* __restrict__ x,
                                              const float* __restrict__ W,
                                              const float* __restrict__ bprev) {
    extern __shared__ float smem[];
    float* As   = smem;                         // [BM][ASTR]
    float* Ws   = smem + BM * ASTR;             // [128][WSTR]
    float* sdis = smem + BM * ASTR + 128 * WSTR;// [128]
    float* sb1  = sdis + 128;                   // [128]

    int tid = threadIdx.x;
    int row0 = blockIdx.x * BM;

    if (tid < 128) {
        int gr = row0 + tid;
        sdis[tid] = (gr < N_NODES) ? g_dis[gr] : 0.f;
        if (LAYER == 1) sb1[tid] = bprev[tid];
    }

    // stage W (128x128 fp32 -> tf32)
    const float4* W4 = (const float4*)W;
#pragma unroll
    for (int i = 0; i < 16; i++) {
        int j = tid + i * 256;
        int r = j >> 5, c4 = j & 31;
        float4 v = W4[j];
        *(float4*)&Ws[r * WSTR + c4 * 4] =
            make_float4(f2tf32(v.x), f2tf32(v.y), f2tf32(v.z), f2tf32(v.w));
    }
    __syncthreads();    // sdis/sb1 ready for LAYER1 A staging

    if (LAYER == 0) {
        // A tile from x: 128x128 fp32 = 4096 float4
#pragma unroll
        for (int i = 0; i < 16; i++) {
            int j = tid + i * 256;
            int r = j >> 5, c4 = j & 31;
            int gr = row0 + r;
            float4 v = make_float4(0.f, 0.f, 0.f, 0.f);
            if (gr < N_NODES) v = *(const float4*)&x[(size_t)gr * H + c4 * 4];
            *(float4*)&As[r * ASTR + c4 * 4] =
                make_float4(f2tf32(v.x), f2tf32(v.y), f2tf32(v.z), f2tf32(v.w));
        }
    } else {
        // A tile = relu(dis*s1 + b1), s1 fp16: 128x128 halfs = 2048 uint4
#pragma unroll
        for (int i = 0; i < 8; i++) {
            int j = tid + i * 256;
            int r = j >> 4, c8 = j & 15;
            int gr = row0 + r;
            float d = sdis[r];
            float o[8];
            if (gr < N_NODES) {
                uint4 u = *(const uint4*)&g_s1[(size_t)gr * H + c8 * 8];
                float2 f0 = __half22float2(*(__half2*)&u.x);
                float2 f1 = __half22float2(*(__half2*)&u.y);
                float2 f2 = __half22float2(*(__half2*)&u.z);
                float2 f3 = __half22float2(*(__half2*)&u.w);
                float in[8] = {f0.x, f0.y, f1.x, f1.y, f2.x, f2.y, f3.x, f3.y};
#pragma unroll
                for (int t = 0; t < 8; t++)
                    o[t] = f2tf32(fmaxf(fmaf(d, in[t], sb1[c8 * 8 + t]), 0.f));
            } else {
#pragma unroll
                for (int t = 0; t < 8; t++) o[t] = 0.f;
            }
            *(float4*)&As[r * ASTR + c8 * 8]     = make_float4(o[0], o[1], o[2], o[3]);
            *(float4*)&As[r * ASTR + c8 * 8 + 4] = make_float4(o[4], o[5], o[6], o[7]);
        }
    }
    __syncthreads();

    int lane = tid & 31, wid = tid >> 5;
    int wm = wid >> 1, wn = wid & 1;            // 4 x 2 warp grid
    int g8 = lane >> 2, tig = lane & 3;

    float acc[2][8][4];
#pragma unroll
    for (int mf = 0; mf < 2; mf++)
#pragma unroll
        for (int nf = 0; nf < 8; nf++)
#pragma unroll
            for (int q = 0; q < 4; q++) acc[mf][nf][q] = 0.f;

#pragma unroll 1
    for (int kk = 0; kk < 16; kk++) {
        int k0 = kk * 8;
        unsigned b[8][2];
#pragma unroll
        for (int nf = 0; nf < 8; nf++) {
            int n = wn * 64 + nf * 8 + g8;
            b[nf][0] = __float_as_uint(Ws[(k0 + tig) * WSTR + n]);
            b[nf][1] = __float_as_uint(Ws[(k0 + tig + 4) * WSTR + n]);
        }
#pragma unroll
        for (int mf = 0; mf < 2; mf++) {
            int r = wm * 32 + mf * 16 + g8;
            unsigned a0 = __float_as_uint(As[r * ASTR + k0 + tig]);
            unsigned a1 = __float_as_uint(As[(r + 8) * ASTR + k0 + tig]);
            unsigned a2 = __float_as_uint(As[r * ASTR + k0 + tig + 4]);
            unsigned a3 = __float_as_uint(As[(r + 8) * ASTR + k0 + tig + 4]);
#pragma unroll
            for (int nf = 0; nf < 8; nf++)
                mma_tf32(acc[mf][nf][0], acc[mf][nf][1], acc[mf][nf][2], acc[mf][nf][3],
                         a0, a1, a2, a3, b[nf][0], b[nf][1]);
        }
    }

    // epilogue: scale by dis, pack half2, dual-write (gather src + self-loop seed)
    __half* sout = (LAYER == 0) ? g_s1 : g_s2;
#pragma unroll
    for (int mf = 0; mf < 2; mf++) {
#pragma unroll
        for (int hh = 0; hh < 2; hh++) {        // d0/d1 (row g) vs d2/d3 (row g+8)
            int lr = wm * 32 + mf * 16 + g8 + hh * 8;
            int gr = row0 + lr;
            if (gr >= N_NODES) continue;
            float dsc = sdis[lr];
#pragma unroll
            for (int nf = 0; nf < 8; nf++) {
                float v0 = acc[mf][nf][hh * 2 + 0] * dsc;
                float v1 = acc[mf][nf][hh * 2 + 1] * dsc;
                __half2 hv = __floats2half2_rn(v0, v1);
                size_t off = (size_t)gr * H + wn * 64 + nf * 8 + 2 * tig;
                *(__half2*)&g_h[off]  = hv;
                *(__half2*)&sout[off] = hv;
            }
        }
    }
}

// ---------------- edge scatter: s[dst] += h'[src], fp16x2 vector reduction -------
// 16 threads per edge: each thread gathers uint4 (8 halfs = 16B) and fires one
// red.global.add.noftz.v4.f16x2 (fire-and-forget, no return trip).
template<int LAYER>
__global__ __launch_bounds__(256) void k_scatter(const int* __restrict__ ei) {
    unsigned gt = blockIdx.x * 256u + threadIdx.x;
    unsigned e = gt >> 4;
    int l = threadIdx.x & 15;
    if (e >= N_EDGES) return;
    int s = __ldg(&ei[e]);
    int d = __ldg(&ei[N_EDGES + e]);
    if ((unsigned)s >= N_NODES || (unsigned)d >= N_NODES) return;
    __half* dst = (LAYER == 0) ? g_s1 : g_s2;
    uint4 v = *(const uint4*)&g_h[(size_t)s * H + l * 8];
    __half* p = &dst[(size_t)d * H + l * 8];
    asm volatile("red.global.add.noftz.v4.f16x2 [%0], {%1,%2,%3,%4};"
                 :: "l"(p), "r"(v.x), "r"(v.y), "r"(v.z), "r"(v.w)
                 : "memory");
}

// ---------------- global mean pool with fused relu(dis*s2 + b2) ----------------
#define POOL_CHUNK 64
__global__ __launch_bounds__(128) void k_pool(const int* __restrict__ batch,
                                              const float* __restrict__ b2) {
    int r0 = blockIdx.x * POOL_CHUNK;
    if (r0 >= N_NODES) return;
    int r1 = min(r0 + POOL_CHUNK, N_NODES);
    int f = threadIdx.x;                 // one thread per feature
    float bb = b2[f];
    int cur = batch[r0];
    float acc = 0.f, c = 0.f;
    for (int r = r0; r < r1; r++) {
        int g = batch[r];                // sorted -> rare flushes, uniform branch
        if (g != cur) {
            atomicAdd(&g_pool[cur * H + f], acc);
            if (f == 0) atomicAdd(&g_cnt[cur], c);
            acc = 0.f; c = 0.f; cur = g;
        }
        float v = __half2float(g_s2[(size_t)r * H + f]);
        v = fmaxf(fmaf(g_dis[r], v, bb), 0.f);
        acc += v; c += 1.f;
    }
    atomicAdd(&g_pool[cur * H + f], acc);
    if (f == 0) atomicAdd(&g_cnt[cur], c);
}

// ---------------- head MLP: 64 blocks, one per graph ----------------
__global__ __launch_bounds__(256) void k_mlp(const float* __restrict__ sv,
                                             const float* __restrict__ act,
                                             const float* __restrict__ Wf1, const float* __restrict__ bf1,
                                             const float* __restrict__ Wf2, const float* __restrict__ bf2,
                                             const float* __restrict__ Wo,  const float* __restrict__ bo,
                                             float* __restrict__ out) {
    int g = blockIdx.x;
    int t = threadIdx.x;
    __shared__ float z[ZDIM];
    __shared__ float z1[256];
    __shared__ float z2[256];
    __shared__ float red[8];

    if (t < ZDIM) {
        float v;
        if (t < 128)      v = g_pool[g * H + t] / fmaxf(g_cnt[g], 1.0f);
        else if (t < 192) v = sv[g * 64 + (t - 128)];
        else              v = act[g * 32 + (t - 192)];
        z[t] = v;
    }
    __syncthreads();

    float a = bf1[t];
#pragma unroll 8
    for (int k = 0; k < ZDIM; k++) a = fmaf(z[k], Wf1[k * 256 + t], a);
    z1[t] = fmaxf(a, 0.f);
    __syncthreads();

    a = bf2[t];
#pragma unroll 8
    for (int k = 0; k < 256; k++) a = fmaf(z1[k], Wf2[k * 256 + t], a);
    z2[t] = fmaxf(a, 0.f);
    __syncthreads();

    float p = z2[t] * Wo[t];
#pragma unroll
    for (int o = 16; o > 0; o >>= 1) p += __shfl_down_sync(0xffffffffu, p, o);
    if ((t & 31) == 0) red[t >> 5] = p;
    __syncthreads();
    if (t == 0) {
        float sacc = 0.f;
#pragma unroll
        for (int i = 0; i < 8; i++) sacc += red[i];
        out[g] = sacc + bo[0];
    }
}

// ---------------- launch ----------------
extern "C" void kernel_launch(void* const* d_in, const int* in_sizes, int n_in,
                              void* d_out, int out_size) {
    const float* x     = (const float*)d_in[0];
    const int*   ei    = (const int*)d_in[1];
    const int*   batch = (const int*)d_in[2];
    const float* sv    = (const float*)d_in[3];
    const float* act   = (const float*)d_in[4];
    const float* W1    = (const float*)d_in[5];
    const float* b1    = (const float*)d_in[6];
    const float* W2    = (const float*)d_in[7];
    const float* b2    = (const float*)d_in[8];
    const float* Wf1   = (const float*)d_in[9];
    const float* bf1   = (const float*)d_in[10];
    const float* Wf2   = (const float*)d_in[11];
    const float* bf2   = (const float*)d_in[12];
    const float* Wo    = (const float*)d_in[13];
    const float* bo    = (const float*)d_in[14];
    float* out = (float*)d_out;

    cudaFuncSetAttribute(k_gemm<0>, cudaFuncAttributeMaxDynamicSharedMemorySize, GEMM_SMEM);
    cudaFuncSetAttribute(k_gemm<1>, cudaFuncAttributeMaxDynamicSharedMemorySize, GEMM_SMEM);

    k_init <<<(N_NODES + 255) / 256, 256>>>();
    k_deg  <<<(N_EDGES + 255) / 256, 256>>>(ei);
    k_rsqrt<<<(N_NODES + 255) / 256, 256>>>();

    int gemm_blocks = (N_NODES + BM - 1) / BM;                       // 782
    int scat_blocks = (int)(((long long)N_EDGES * 16 + 255) / 256);  // 100000

    k_gemm<0>   <<<gemm_blocks, 256, GEMM_SMEM>>>(x, W1, b1);
    k_scatter<0><<<scat_blocks, 256>>>(ei);
    k_gemm<1>   <<<gemm_blocks, 256, GEMM_SMEM>>>(x, W2, b1);
    k_scatter<1><<<scat_blocks, 256>>>(ei);

    k_pool<<<(N_NODES + POOL_CHUNK - 1) / POOL_CHUNK, 128>>>(batch, b2);
    k_mlp <<<N_GRAPH, 256>>>(sv, act, Wf1, bf1, Wf2, bf2, Wo, bo, out);
}